// round 17
// baseline (speedup 1.0000x reference)
#include <cuda_runtime.h>
#include <cstdint>

#define EMBED     1024
#define STEPS     8
#define NF        16      // 2*STEPS features
#define NFP       8       // f32x2 feature pairs
#define TOK_TILE  128     // tokens per CTA
#define NTHREADS  256     // 256 threads * 4 dims = 1024 embed dims
#define DPT       4       // embed dims per thread
#define CHUNK     8       // tokens per bulk store (32 KB)
#define NCHUNK    (TOK_TILE / CHUNK)          // 16
#define STG_FLOATS (CHUNK * EMBED)            // 8192 floats = 32 KB per buffer
#define SM_STAGE_OFF (TOK_TILE * NF)          // feats occupy [0, 2048) floats
#define SM_TOTAL_BYTES ((SM_STAGE_OFF + 2 * STG_FLOATS) * 4)   // 72 KB

__device__ __forceinline__ unsigned long long pack2(float a, float b) {
    unsigned long long r;
    asm("mov.b64 %0, {%1, %2};" : "=l"(r) : "f"(a), "f"(b));
    return r;
}

__device__ __forceinline__ uint32_t smem_u32(const void* p) {
    uint32_t a;
    asm("{ .reg .u64 t; cvta.to.shared.u64 t, %1; cvt.u32.u64 %0, t; }" : "=r"(a) : "l"(p));
    return a;
}

__device__ __forceinline__ void load_feats(const float* fs, unsigned long long* f2) {
    const ulonglong2* fp = reinterpret_cast<const ulonglong2*>(fs);
    ulonglong2 qa = fp[0], qb = fp[1], qc = fp[2], qd = fp[3];
    f2[0] = qa.x; f2[1] = qa.y; f2[2] = qb.x; f2[3] = qb.y;
    f2[4] = qc.x; f2[5] = qc.y; f2[6] = qd.x; f2[7] = qd.y;
}

// 32 FFMA2 over 4 independent chains -> float4 result
__device__ __forceinline__ float4 gemm_token(const unsigned long long* f2,
                                             const unsigned long long wreg[DPT][NFP]) {
    unsigned long long a0 = 0ull, a1 = 0ull, a2 = 0ull, a3 = 0ull;
    #pragma unroll
    for (int p = 0; p < NFP; ++p) {
        asm("fma.rn.f32x2 %0, %1, %2, %0;" : "+l"(a0) : "l"(f2[p]), "l"(wreg[0][p]));
        asm("fma.rn.f32x2 %0, %1, %2, %0;" : "+l"(a1) : "l"(f2[p]), "l"(wreg[1][p]));
        asm("fma.rn.f32x2 %0, %1, %2, %0;" : "+l"(a2) : "l"(f2[p]), "l"(wreg[2][p]));
        asm("fma.rn.f32x2 %0, %1, %2, %0;" : "+l"(a3) : "l"(f2[p]), "l"(wreg[3][p]));
    }
    float l0, h0, l1, h1, l2, h2, l3, h3;
    asm("mov.b64 {%0, %1}, %2;" : "=f"(l0), "=f"(h0) : "l"(a0));
    asm("mov.b64 {%0, %1}, %2;" : "=f"(l1), "=f"(h1) : "l"(a1));
    asm("mov.b64 {%0, %1}, %2;" : "=f"(l2), "=f"(h2) : "l"(a2));
    asm("mov.b64 {%0, %1}, %2;" : "=f"(l3), "=f"(h3) : "l"(a3));
    return make_float4(l0 + h0, l1 + h1, l2 + h2, l3 + h3);
}

__global__ void __launch_bounds__(NTHREADS, 2)
fractal_embed_v17_kernel(const int*   __restrict__ token_ids,
                         const float* __restrict__ c_table,
                         const float* __restrict__ W,
                         const float* __restrict__ scale_p,
                         float*       __restrict__ out,
                         int n_tokens)
{
    extern __shared__ __align__(16) float smf[];
    float* feats_s  = smf;                    // [TOK_TILE][NF]
    float* staging  = smf + SM_STAGE_OFF;     // 2 x [CHUNK][EMBED]

    const int tid      = threadIdx.x;
    const int tok_base = blockIdx.x * TOK_TILE;
    if (tok_base >= n_tokens) return;
    const float scale  = *scale_p;

    // ---- Phase A: Julia features (128 threads, one token each) ----
    if (tid < TOK_TILE && tok_base + tid < n_tokens) {
        const int   tok = token_ids[tok_base + tid];
        const float cr  = c_table[2 * tok];
        const float ci  = c_table[2 * tok + 1];
        float zr = 0.f, zi = 0.f;
        #pragma unroll
        for (int s = 0; s < STEPS; ++s) {
            const float nzr = zr * zr - zi * zi + cr;
            const float nzi = 2.f * zr * zi + ci;
            zr = nzr; zi = nzi;
            feats_s[tid * NF + 2 * s]     = zr;
            feats_s[tid * NF + 2 * s + 1] = zi;
        }
    }

    // ---- W slice: 4 rows x 16 feats, scale folded, f32x2-packed (32 u64) ----
    const int d0 = tid * DPT;
    unsigned long long wreg[DPT][NFP];
    {
        const float2* wp = reinterpret_cast<const float2*>(W + (size_t)d0 * NF);
        #pragma unroll
        for (int j = 0; j < DPT; ++j) {
            #pragma unroll
            for (int p = 0; p < NFP; ++p) {
                float2 w = wp[j * NFP + p];
                wreg[j][p] = pack2(w.x * scale, w.y * scale);
            }
        }
    }
    __syncthreads();

    const int tmax = n_tokens - tok_base;

    if (tmax >= TOK_TILE) {
        // ---- Phase B: chunked compute -> STS staging -> async bulk store ----
        #pragma unroll 1
        for (int c = 0; c < NCHUNK; ++c) {
            // buffer-reuse guard: allow at most 1 outstanding bulk group
            if (c >= 2 && tid == 0)
                asm volatile("cp.async.bulk.wait_group 1;" ::: "memory");
            __syncthreads();

            float* stg = staging + (c & 1) * STG_FLOATS;

            #pragma unroll 1
            for (int t = 0; t < CHUNK; t += 2) {
                const int tok = c * CHUNK + t;
                unsigned long long fA[NFP], fB[NFP];
                load_feats(feats_s + tok * NF,       fA);
                load_feats(feats_s + (tok + 1) * NF, fB);

                float4 oA = gemm_token(fA, wreg);
                float4 oB = gemm_token(fB, wreg);

                *reinterpret_cast<float4*>(stg + t * EMBED + d0)       = oA;  // STS.128
                *reinterpret_cast<float4*>(stg + (t + 1) * EMBED + d0) = oB;  // STS.128
            }
            __syncthreads();

            if (tid == 0) {
                asm volatile("fence.proxy.async.shared::cta;" ::: "memory");
                float* gdst = out + (size_t)(tok_base + c * CHUNK) * EMBED;
                asm volatile("cp.async.bulk.global.shared::cta.bulk_group [%0], [%1], %2;"
                             :: "l"(gdst), "r"(smem_u32(stg)), "r"((uint32_t)(STG_FLOATS * 4))
                             : "memory");
                asm volatile("cp.async.bulk.commit_group;" ::: "memory");
            }
        }
        if (tid == 0)
            asm volatile("cp.async.bulk.wait_group 0;" ::: "memory");
    } else {
        // remainder tile: plain STG path (not taken for 65536/128 grid)
        float* outp = out + (size_t)tok_base * EMBED + d0;
        #pragma unroll 1
        for (int t = 0; t < tmax; ++t) {
            unsigned long long fA[NFP];
            load_feats(feats_s + t * NF, fA);
            float4 o = gemm_token(fA, wreg);
            *reinterpret_cast<float4*>(outp) = o;
            outp += EMBED;
        }
    }
}

extern "C" void kernel_launch(void* const* d_in, const int* in_sizes, int n_in,
                              void* d_out, int out_size)
{
    const int*   token_ids = (const int*)  d_in[0];
    const float* c_table   = (const float*)d_in[1];
    const float* W         = (const float*)d_in[2];
    const float* scale_p   = (const float*)d_in[3];
    float*       out       = (float*)d_out;

    const int n_tokens = in_sizes[0];

    static int attr_set = 0;
    if (!attr_set) {
        cudaFuncSetAttribute(fractal_embed_v17_kernel,
                             cudaFuncAttributeMaxDynamicSharedMemorySize, SM_TOTAL_BYTES);
        attr_set = 1;
    }

    const int blocks = (n_tokens + TOK_TILE - 1) / TOK_TILE;
    fractal_embed_v17_kernel<<<blocks, NTHREADS, SM_TOTAL_BYTES>>>(
        token_ids, c_table, W, scale_p, out, n_tokens);
}